// round 8
// baseline (speedup 1.0000x reference)
#include <cuda_runtime.h>
#include <cstdint>

#define DB 2     // batch
#define DL 64    // L
#define DT 32    // T
#define DD 256   // D
#define NTILES 1024                 // (bi, j0) tiles, 8 j's each
#define STAGES 3
#define ITEM_F4 2048                // float4 per item per tensor (32*64)
#define STAGE_FLOATS 16384          // key(8192) + value(8192) floats = 64KB
#define SMEM_FLOATS (STAGES * STAGE_FLOATS + 2048 + 64)
#define SMEM_BYTES  (SMEM_FLOATS * 4)   // 205,312 B < 227KB limit

// Scratch (device globals: no allocation allowed)
__device__ float g_Qk[DB * DL * DD];      // per (b,i): ((q@Wq^T+bq)/16)@Wk
__device__ float g_WcombT[DD * DD];       // WcombT[d,f] = sum_e Wv[e,d]*Wf[f,e]
__device__ float g_bcomb[DD];             // bcomb[f] = sum_e Wf[f,e]*bv[e] + bf[f]
__device__ int   g_ticket;                // dynamic tile ticket

// ---------------------------------------------------------------------------
// cp.async helpers
// ---------------------------------------------------------------------------
__device__ __forceinline__ void cp_async16(uint32_t dst, const void* src) {
    asm volatile("cp.async.cg.shared.global [%0], [%1], 16;"
                 :: "r"(dst), "l"(src) : "memory");
}
__device__ __forceinline__ void cp_commit() {
    asm volatile("cp.async.commit_group;" ::: "memory");
}
__device__ __forceinline__ void cp_wait2() {
    asm volatile("cp.async.wait_group 2;" ::: "memory");
}

__device__ __forceinline__ float dot8(const float4 a0, const float4 a1,
                                      const float4 b0, const float4 b1) {
    return a0.x * b0.x + a0.y * b0.y + a0.z * b0.z + a0.w * b0.w
         + a1.x * b1.x + a1.y * b1.y + a1.z * b1.z + a1.w * b1.w;
}

// ---------------------------------------------------------------------------
// Single prologue kernel, block = (32,32) = 1024 threads.
// ---------------------------------------------------------------------------
__global__ void prologue_kernel(const float* __restrict__ query,
                                const float* __restrict__ Wq,
                                const float* __restrict__ bq,
                                const float* __restrict__ Wk,
                                const float* __restrict__ Wv,
                                const float* __restrict__ bv,
                                const float* __restrict__ Wf,
                                const float* __restrict__ bf) {
    const int tx = threadIdx.x, ty = threadIdx.y;
    const int tid = ty * 32 + tx;
    const int blk = blockIdx.x;

    if (blk < 64) {
        __shared__ float Av[2][32][33];
        __shared__ float Bf[2][32][33];
        const int f0 = (blk & 7) * 32;
        const int d0 = (blk >> 3) * 32;

        Av[0][ty][tx] = Wv[(size_t)ty * DD + d0 + tx];
        Bf[0][ty][tx] = Wf[(size_t)(f0 + ty) * DD + tx];
        __syncthreads();

        float acc = 0.f;
#pragma unroll
        for (int s = 0; s < 8; s++) {
            const int cur = s & 1;
            if (s < 7) {
                const int e0 = (s + 1) * 32;
                Av[cur ^ 1][ty][tx] = Wv[(size_t)(e0 + ty) * DD + d0 + tx];
                Bf[cur ^ 1][ty][tx] = Wf[(size_t)(f0 + ty) * DD + e0 + tx];
            }
#pragma unroll
            for (int k = 0; k < 32; k++) acc += Av[cur][k][ty] * Bf[cur][tx][k];
            __syncthreads();
        }
        g_WcombT[(size_t)(d0 + ty) * DD + f0 + tx] = acc;

    } else if (blk < 192) {
        const int bi = blk - 64;
        __shared__ float q[DD];
        __shared__ float Qs[DD];
        __shared__ float part[4][DD];

        if (tid < DD) q[tid] = query[bi * DD + tid];
        __syncthreads();

#pragma unroll
        for (int i = 0; i < 8; i++) {
            const int e = ty * 8 + i;
            const float* wq = Wq + (size_t)e * DD;
            float p = 0.f;
#pragma unroll
            for (int c = 0; c < 8; c++) p += q[tx + 32 * c] * wq[tx + 32 * c];
#pragma unroll
            for (int off = 16; off; off >>= 1)
                p += __shfl_xor_sync(0xffffffffu, p, off);
            if (tx == 0) Qs[e] = (p + bq[e]) * 0.0625f;
        }
        __syncthreads();

        const int quarter = ty >> 3;
        const int d = tx + (ty & 7) * 32;
        const int e0 = quarter * 64;
        float acc = 0.f;
#pragma unroll 8
        for (int e = 0; e < 64; e++)
            acc += Qs[e0 + e] * Wk[(size_t)(e0 + e) * DD + d];
        part[quarter][d] = acc;
        __syncthreads();
        if (tid < DD)
            g_Qk[bi * DD + tid] = part[0][tid] + part[1][tid] + part[2][tid] + part[3][tid];

    } else {
        if (tid == 0) g_ticket = 0;
        __shared__ float bvs[DD];
        if (tid < DD) bvs[tid] = bv[tid];
        __syncthreads();
#pragma unroll
        for (int i = 0; i < 8; i++) {
            const int f = ty * 8 + i;
            const float* wf = Wf + (size_t)f * DD;
            float p = 0.f;
#pragma unroll
            for (int c = 0; c < 8; c++) p += bvs[tx + 32 * c] * wf[tx + 32 * c];
#pragma unroll
            for (int off = 16; off; off >>= 1)
                p += __shfl_xor_sync(0xffffffffu, p, off);
            if (tx == 0) g_bcomb[f] = p + bf[f];
        }
    }
}

// ---------------------------------------------------------------------------
// Main kernel: 1 block/SM, 3-stage cp.async pipeline (64KB/stage = one j's
// key+value). MLP comes from async depth, not registers. Items are (tile,jj)
// pairs consumed in order; tiles come from a global ticket. Phase C fires at
// jj==7, overlapped with prefetch of the next tile's items.
// ---------------------------------------------------------------------------
__global__ __launch_bounds__(256)
void attn_pipe_kernel(const float4* __restrict__ key4,
                      const float4* __restrict__ value4,
                      float* __restrict__ out) {
    const int tid  = threadIdx.x;
    const int w    = tid >> 5;
    const int lane = tid & 31;

    extern __shared__ float smem[];
    float* stages   = smem;                           // STAGES * 16384 floats
    float* vbar     = smem + STAGES * STAGE_FLOATS;   // 2048 floats
    float* s_scores = vbar + 2048;                    // 32
    float* s_attn   = s_scores + 32;                  // 32
    __shared__ int s_ring[4];                         // tile per (item>>3)&3
    __shared__ int s_total;                           // total items this block

    if (tid == 0) s_total = 0x7fffffff;

    // ---- prime: post items 0..STAGES-1 ----
    for (int q = 0; q < STAGES; q++) {
        if (tid == 0 && (q & 7) == 0 && s_total == 0x7fffffff) {
            const int t = atomicAdd(&g_ticket, 1);
            s_ring[(q >> 3) & 3] = t;
            if (t >= NTILES) s_total = q;
        }
        __syncthreads();
        if (q < s_total) {
            const int tq  = s_ring[(q >> 3) & 3];
            const int jq  = ((tq & 7) << 3) + (q & 7);
            const size_t bq = (size_t)((tq >> 3) * DL + jq) * ITEM_F4;
            float* sd = stages + (q % STAGES) * STAGE_FLOATS;
            const uint32_t ds = (uint32_t)__cvta_generic_to_shared(sd);
#pragma unroll
            for (int i = 0; i < 8; i++) {
                const int idx = tid + 256 * i;
                cp_async16(ds + idx * 16, key4 + bq + idx);
                cp_async16(ds + 32768 + idx * 16, value4 + bq + idx);
            }
        }
        cp_commit();
    }

    // ---- steady-state consume/post loop ----
    for (int p = 0;; p++) {
        __syncthreads();                  // vbar reuse + s_total visibility
        if (p >= s_total) break;
        cp_wait2();                       // stage p%STAGES complete (this thread)
        __syncthreads();                  // ... and visible to all threads

        const int tile = s_ring[(p >> 3) & 3];
        const int jj   = p & 7;
        const int bi   = tile >> 3;
        const float* ks = stages + (p % STAGES) * STAGE_FLOATS;
        const float* vs = ks + 8192;

        const float4* qk4 = reinterpret_cast<const float4*>(g_Qk) + bi * 64;
        const float4 qk0 = qk4[lane];
        const float4 qk1 = qk4[32 + lane];
        const float4* k4s = reinterpret_cast<const float4*>(ks);

        // scores: warp w owns t = 4w .. 4w+3
#pragma unroll
        for (int i = 0; i < 4; i++) {
            const int t = w * 4 + i;
            const float4 a0 = k4s[t * 64 + lane];
            const float4 a1 = k4s[t * 64 + 32 + lane];
            float s = dot8(a0, a1, qk0, qk1);
#pragma unroll
            for (int off = 16; off; off >>= 1)
                s += __shfl_xor_sync(0xffffffffu, s, off);
            if (lane == 0) s_scores[t] = s;
        }
        __syncthreads();

        // softmax over T=32 (warp 0)
        if (w == 0) {
            const float sc = s_scores[lane];
            float mm = sc;
#pragma unroll
            for (int off = 16; off; off >>= 1)
                mm = fmaxf(mm, __shfl_xor_sync(0xffffffffu, mm, off));
            const float ex = __expf(sc - mm);
            float ss = ex;
#pragma unroll
            for (int off = 16; off; off >>= 1)
                ss += __shfl_xor_sync(0xffffffffu, ss, off);
            s_attn[lane] = ex / ss;
        }
        __syncthreads();

        // vbar[d = tid] = sum_t attn[t] * V[t][d]
        {
            float a0c = 0.f, a1c = 0.f, a2c = 0.f, a3c = 0.f;
#pragma unroll
            for (int t = 0; t < DT; t += 4) {
                a0c += s_attn[t + 0] * vs[(t + 0) * DD + tid];
                a1c += s_attn[t + 1] * vs[(t + 1) * DD + tid];
                a2c += s_attn[t + 2] * vs[(t + 2) * DD + tid];
                a3c += s_attn[t + 3] * vs[(t + 3) * DD + tid];
            }
            vbar[jj * DD + tid] = (a0c + a1c) + (a2c + a3c);
        }
        __syncthreads();                  // done reading stage p%STAGES

        // post item q = p + STAGES into the freed stage
        {
            const int q = p + STAGES;
            if (tid == 0 && (q & 7) == 0 && s_total == 0x7fffffff) {
                const int t = atomicAdd(&g_ticket, 1);
                s_ring[(q >> 3) & 3] = t;
                if (t >= NTILES) s_total = q;
            }
            __syncthreads();
            if (q < s_total) {
                const int tq  = s_ring[(q >> 3) & 3];
                const int jq  = ((tq & 7) << 3) + (q & 7);
                const size_t bq = (size_t)((tq >> 3) * DL + jq) * ITEM_F4;
                float* sd = stages + (q % STAGES) * STAGE_FLOATS;
                const uint32_t ds = (uint32_t)__cvta_generic_to_shared(sd);
#pragma unroll
                for (int i = 0; i < 8; i++) {
                    const int idx = tid + 256 * i;
                    cp_async16(ds + idx * 16, key4 + bq + idx);
                    cp_async16(ds + 32768 + idx * 16, value4 + bq + idx);
                }
            }
            cp_commit();
        }

        // Phase C once per tile (jj==7), overlapped with prefetch above
        if (jj == 7) {
            const int f = tid;
            float acc[8];
            const float bc = __ldg(&g_bcomb[f]);
#pragma unroll
            for (int k = 0; k < 8; k++) acc[k] = bc;

            const float4* vb4 = reinterpret_cast<const float4*>(vbar);
#pragma unroll 4
            for (int d4 = 0; d4 < 64; d4++) {
                const float* wt = &g_WcombT[(size_t)(d4 * 4) * DD + f];
                const float w0 = __ldg(wt);
                const float w1 = __ldg(wt + DD);
                const float w2 = __ldg(wt + 2 * DD);
                const float w3 = __ldg(wt + 3 * DD);
#pragma unroll
                for (int k = 0; k < 8; k++) {
                    const float4 v = vb4[k * 64 + d4];   // smem broadcast
                    acc[k] += v.x * w0 + v.y * w1 + v.z * w2 + v.w * w3;
                }
            }
            const int j0 = (tile & 7) << 3;
            const size_t obase = (size_t)(bi * DL + j0) * DD + f;
#pragma unroll
            for (int k = 0; k < 8; k++)
                __stcs(&out[obase + (size_t)k * DD], acc[k]);
        }
    }
}

// ---------------------------------------------------------------------------
// Launch. Input order: key, value, query, Wk, bk, Wv, bv, Wq, bq, Wf, bf
// ---------------------------------------------------------------------------
extern "C" void kernel_launch(void* const* d_in, const int* in_sizes, int n_in,
                              void* d_out, int out_size) {
    const float* key   = (const float*)d_in[0];
    const float* value = (const float*)d_in[1];
    const float* query = (const float*)d_in[2];
    const float* Wk    = (const float*)d_in[3];
    // bk (d_in[4]) cancels under softmax — unused.
    const float* Wv    = (const float*)d_in[5];
    const float* bv    = (const float*)d_in[6];
    const float* Wq    = (const float*)d_in[7];
    const float* bq    = (const float*)d_in[8];
    const float* Wf    = (const float*)d_in[9];
    const float* bf    = (const float*)d_in[10];
    float* out = (float*)d_out;

    cudaFuncSetAttribute(attn_pipe_kernel,
                         cudaFuncAttributeMaxDynamicSharedMemorySize, SMEM_BYTES);

    prologue_kernel<<<193, dim3(32, 32)>>>(query, Wq, bq, Wk, Wv, bv, Wf, bf);

    attn_pipe_kernel<<<148, 256, SMEM_BYTES>>>(
        reinterpret_cast<const float4*>(key),
        reinterpret_cast<const float4*>(value),
        out);
}

// round 9
// speedup vs baseline: 2.1709x; 2.1709x over previous
#include <cuda_runtime.h>
#include <cstdint>

#define DB 2     // batch
#define DL 64    // L
#define DT 32    // T
#define DD 256   // D
#define G  8     // j-columns per tile
#define NTILES (DB * DL * DL / G)   // 1024

// Scratch (device globals: no allocation allowed)
__device__ float g_Qk[DB * DL * DD];      // per (b,i): ((q@Wq^T+bq)/16)@Wk
__device__ float g_WcombP[64 * DD * 4];   // packed: [d4][f][4] = Wcomb[4*d4+r][f]
__device__ float g_bcomb[DD];             // bcomb[f] = sum_e Wf[f,e]*bv[e] + bf[f]
__device__ int   g_ticket;                // dynamic tile ticket

// ---------------------------------------------------------------------------
// f32x2 packed-FMA helpers (sm_100+; FFMA2 reachable only via PTX)
// ---------------------------------------------------------------------------
__device__ __forceinline__ unsigned long long ffma2(unsigned long long a,
                                                    unsigned long long b,
                                                    unsigned long long c) {
    unsigned long long d;
    asm("fma.rn.f32x2 %0, %1, %2, %3;" : "=l"(d) : "l"(a), "l"(b), "l"(c));
    return d;
}
__device__ __forceinline__ unsigned long long mul2(unsigned long long a,
                                                   unsigned long long b) {
    unsigned long long d;
    asm("mul.rn.f32x2 %0, %1, %2;" : "=l"(d) : "l"(a), "l"(b));
    return d;
}
__device__ __forceinline__ unsigned long long f2_pack(float lo, float hi) {
    unsigned long long r;
    asm("mov.b64 %0, {%1, %2};" : "=l"(r) : "f"(lo), "f"(hi));
    return r;
}
__device__ __forceinline__ float f2_hsum(unsigned long long v) {
    float lo, hi;
    asm("mov.b64 {%0, %1}, %2;" : "=f"(lo), "=f"(hi) : "l"(v));
    return lo + hi;
}
__device__ __forceinline__ ulonglong2 ldcs_u2(const ulonglong2* p) {
    ulonglong2 r;
    asm("ld.global.cs.v2.u64 {%0, %1}, [%2];" : "=l"(r.x), "=l"(r.y) : "l"(p));
    return r;
}

// ---------------------------------------------------------------------------
// Single prologue kernel, block = (32,32) = 1024 threads.
// ---------------------------------------------------------------------------
__global__ void prologue_kernel(const float* __restrict__ query,
                                const float* __restrict__ Wq,
                                const float* __restrict__ bq,
                                const float* __restrict__ Wk,
                                const float* __restrict__ Wv,
                                const float* __restrict__ bv,
                                const float* __restrict__ Wf,
                                const float* __restrict__ bf) {
    const int tx = threadIdx.x, ty = threadIdx.y;
    const int tid = ty * 32 + tx;
    const int blk = blockIdx.x;

    if (blk < 64) {
        // Wcomb[d,f] = sum_e Wv[e,d]*Wf[f,e], stored packed: P[d>>2][f][d&3]
        __shared__ float Av[2][32][33];
        __shared__ float Bf[2][32][33];
        const int f0 = (blk & 7) * 32;
        const int d0 = (blk >> 3) * 32;

        Av[0][ty][tx] = Wv[(size_t)ty * DD + d0 + tx];
        Bf[0][ty][tx] = Wf[(size_t)(f0 + ty) * DD + tx];
        __syncthreads();

        float acc = 0.f;
#pragma unroll
        for (int s = 0; s < 8; s++) {
            const int cur = s & 1;
            if (s < 7) {
                const int e0 = (s + 1) * 32;
                Av[cur ^ 1][ty][tx] = Wv[(size_t)(e0 + ty) * DD + d0 + tx];
                Bf[cur ^ 1][ty][tx] = Wf[(size_t)(f0 + ty) * DD + e0 + tx];
            }
#pragma unroll
            for (int k = 0; k < 32; k++) acc += Av[cur][k][ty] * Bf[cur][tx][k];
            __syncthreads();
        }
        const int d = d0 + ty;
        const int f = f0 + tx;
        g_WcombP[(size_t)(d >> 2) * (DD * 4) + f * 4 + (d & 3)] = acc;

    } else if (blk < 192) {
        const int bi = blk - 64;
        __shared__ float q[DD];
        __shared__ float Qs[DD];
        __shared__ float part[4][DD];

        if (tid < DD) q[tid] = query[bi * DD + tid];
        __syncthreads();

#pragma unroll
        for (int i = 0; i < 8; i++) {
            const int e = ty * 8 + i;
            const float* wq = Wq + (size_t)e * DD;
            float p = 0.f;
#pragma unroll
            for (int c = 0; c < 8; c++) p += q[tx + 32 * c] * wq[tx + 32 * c];
#pragma unroll
            for (int off = 16; off; off >>= 1)
                p += __shfl_xor_sync(0xffffffffu, p, off);
            if (tx == 0) Qs[e] = (p + bq[e]) * 0.0625f;
        }
        __syncthreads();

        const int quarter = ty >> 3;
        const int d = tx + (ty & 7) * 32;
        const int e0 = quarter * 64;
        float acc = 0.f;
#pragma unroll 8
        for (int e = 0; e < 64; e++)
            acc += Qs[e0 + e] * Wk[(size_t)(e0 + e) * DD + d];
        part[quarter][d] = acc;
        __syncthreads();
        if (tid < DD)
            g_Qk[bi * DD + tid] = part[0][tid] + part[1][tid] + part[2][tid] + part[3][tid];

    } else {
        if (tid == 0) g_ticket = 0;
        __shared__ float bvs[DD];
        if (tid < DD) bvs[tid] = bv[tid];
        __syncthreads();
#pragma unroll
        for (int i = 0; i < 8; i++) {
            const int f = ty * 8 + i;
            const float* wf = Wf + (size_t)f * DD;
            float p = 0.f;
#pragma unroll
            for (int c = 0; c < 8; c++) p += bvs[tx + 32 * c] * wf[tx + 32 * c];
#pragma unroll
            for (int off = 16; off; off >>= 1)
                p += __shfl_xor_sync(0xffffffffu, p, off);
            if (tx == 0) g_bcomb[f] = p + bf[f];
        }
    }
}

// ---------------------------------------------------------------------------
// Phase-A helpers: eager binary-tree score fold (bit-reversed t order),
// packed-FMA dots.
// ---------------------------------------------------------------------------
__device__ __forceinline__ float fold2(float x, float y, int o, int lane) {
    const bool hi = (lane & o) != 0;
    const float send = hi ? x : y;
    const float recv = __shfl_xor_sync(0xffffffffu, send, o);
    return (hi ? y : x) + recv;
}

__device__ __forceinline__ float dot_one(const ulonglong2* __restrict__ kp,
                                         int lane,
                                         const ulonglong2 q0, const ulonglong2 q1,
                                         int t) {
    const ulonglong2 a0 = ldcs_u2(kp + t * 64 + lane);
    const ulonglong2 a1 = ldcs_u2(kp + t * 64 + 32 + lane);
    const unsigned long long r =
        ffma2(a0.x, q0.x,
        ffma2(a0.y, q0.y,
        ffma2(a1.x, q1.x,
        mul2 (a1.y, q1.y))));
    return f2_hsum(r);
}

__device__ __forceinline__ float score_pair(const ulonglong2* __restrict__ kp,
                                            int lane,
                                            const ulonglong2 q0, const ulonglong2 q1,
                                            int t) {
    return fold2(dot_one(kp, lane, q0, q1, t),
                 dot_one(kp, lane, q0, q1, t + 16), 16, lane);
}

// ---------------------------------------------------------------------------
// Main kernel: persistent blocks + ticket; 64-reg cap, 4 blocks/SM resident.
// grid = 592, block = 256 (warp w owns j = j0 + w per tile).
// ---------------------------------------------------------------------------
__global__ __launch_bounds__(256, 4)
void attn_main_kernel(const ulonglong2* __restrict__ key2,
                      const ulonglong2* __restrict__ value2,
                      float* __restrict__ out) {
    const int tid  = threadIdx.x;
    const int w    = tid >> 5;
    const int lane = tid & 31;

    __shared__ int       s_tile;
    __shared__ ulonglong2 vbar_sh[G * 64];     // [jj][64 x (2 f32x2 pairs)]

    for (;;) {
        __syncthreads();                        // vbar_sh reuse + s_tile safety
        if (tid == 0) s_tile = atomicAdd(&g_ticket, 1);
        __syncthreads();
        const int tile = s_tile;
        if (tile >= NTILES) return;

        const int bi = tile >> 3;               // (b*L + i), 0..127
        const int j0 = (tile & 7) * G;
        const int j  = j0 + w;

        const ulonglong2* qk2 = reinterpret_cast<const ulonglong2*>(g_Qk) + bi * 64;
        const ulonglong2 q0 = qk2[lane];
        const ulonglong2 q1 = qk2[32 + lane];

        const size_t base = (size_t)(bi * DL + j) * (DT * 64);   // 16B units
        const ulonglong2* kp = key2 + base;
        const ulonglong2* vp = value2 + base;

        // ---- Phase A: eager tree fold over packed dots ----
        float h0, h1;
        {
            float m08 = fold2(score_pair(kp, lane, q0, q1, 0),
                              score_pair(kp, lane, q0, q1, 8), 8, lane);
            float m4  = fold2(score_pair(kp, lane, q0, q1, 4),
                              score_pair(kp, lane, q0, q1, 12), 8, lane);
            float qa  = fold2(m08, m4, 4, lane);
            float m2  = fold2(score_pair(kp, lane, q0, q1, 2),
                              score_pair(kp, lane, q0, q1, 10), 8, lane);
            float m6  = fold2(score_pair(kp, lane, q0, q1, 6),
                              score_pair(kp, lane, q0, q1, 14), 8, lane);
            float qb  = fold2(m2, m6, 4, lane);
            h0 = fold2(qa, qb, 2, lane);        // all even t
        }
        {
            float m1  = fold2(score_pair(kp, lane, q0, q1, 1),
                              score_pair(kp, lane, q0, q1, 9), 8, lane);
            float m5  = fold2(score_pair(kp, lane, q0, q1, 5),
                              score_pair(kp, lane, q0, q1, 13), 8, lane);
            float qc  = fold2(m1, m5, 4, lane);
            float m3  = fold2(score_pair(kp, lane, q0, q1, 3),
                              score_pair(kp, lane, q0, q1, 11), 8, lane);
            float m7  = fold2(score_pair(kp, lane, q0, q1, 7),
                              score_pair(kp, lane, q0, q1, 15), 8, lane);
            float qd  = fold2(m3, m7, 4, lane);
            h1 = fold2(qc, qd, 2, lane);        // all odd t
        }
        const float myscore = fold2(h0, h1, 1, lane);   // lane l = score[t=l]

        // ---- warp-local softmax over T=32 ----
        float m = myscore;
#pragma unroll
        for (int off = 16; off; off >>= 1)
            m = fmaxf(m, __shfl_xor_sync(0xffffffffu, m, off));
        const float ex = __expf(myscore - m);
        float ssum = ex;
#pragma unroll
        for (int off = 16; off; off >>= 1)
            ssum += __shfl_xor_sync(0xffffffffu, ssum, off);
        const float a = ex / ssum;              // attn[t = lane]

        // ---- Phase B: vbar[d] = sum_t attn[t] * value[t,d] (packed) ----
        unsigned long long b00 = 0ull, b01 = 0ull, b10 = 0ull, b11 = 0ull;
#pragma unroll
        for (int t = 0; t < DT; t++) {
            const float at = __shfl_sync(0xffffffffu, a, t);
            const unsigned long long at2 = f2_pack(at, at);
            const ulonglong2 v0 = ldcs_u2(vp + t * 64 + lane);
            const ulonglong2 v1 = ldcs_u2(vp + t * 64 + 32 + lane);
            b00 = ffma2(v0.x, at2, b00);
            b01 = ffma2(v0.y, at2, b01);
            b10 = ffma2(v1.x, at2, b10);
            b11 = ffma2(v1.y, at2, b11);
        }
        vbar_sh[w * 64 + lane]      = make_ulonglong2(b00, b01);
        vbar_sh[w * 64 + 32 + lane] = make_ulonglong2(b10, b11);
        __syncthreads();

        // ---- Phase C: out[j0+jj, f] = bcomb[f] + vbar[jj] . Wcomb[:,f] ----
        // packed: per d4, one LDG.128 of W pairs + per jj one LDS.128 + 2 FFMA2
        const int f = tid;
        unsigned long long acc2[G];
#pragma unroll
        for (int jj = 0; jj < G; jj++) acc2[jj] = 0ull;

        const ulonglong2* wp2 = reinterpret_cast<const ulonglong2*>(g_WcombP) + f;
#pragma unroll 4
        for (int d4 = 0; d4 < 64; d4++) {
            const ulonglong2 wp = __ldg(wp2 + d4 * DD);
#pragma unroll
            for (int jj = 0; jj < G; jj++) {
                const ulonglong2 v = vbar_sh[jj * 64 + d4];   // smem broadcast
                acc2[jj] = ffma2(v.x, wp.x, acc2[jj]);
                acc2[jj] = ffma2(v.y, wp.y, acc2[jj]);
            }
        }

        const float bc = __ldg(&g_bcomb[f]);
        const size_t obase = (size_t)(bi * DL + j0) * DD + f;
#pragma unroll
        for (int jj = 0; jj < G; jj++)
            __stcs(&out[obase + (size_t)jj * DD], f2_hsum(acc2[jj]) + bc);
    }
}

// ---------------------------------------------------------------------------
// Launch. Input order: key, value, query, Wk, bk, Wv, bv, Wq, bq, Wf, bf
// ---------------------------------------------------------------------------
extern "C" void kernel_launch(void* const* d_in, const int* in_sizes, int n_in,
                              void* d_out, int out_size) {
    const float* key   = (const float*)d_in[0];
    const float* value = (const float*)d_in[1];
    const float* query = (const float*)d_in[2];
    const float* Wk    = (const float*)d_in[3];
    // bk (d_in[4]) cancels under softmax — unused.
    const float* Wv    = (const float*)d_in[5];
    const float* bv    = (const float*)d_in[6];
    const float* Wq    = (const float*)d_in[7];
    const float* bq    = (const float*)d_in[8];
    const float* Wf    = (const float*)d_in[9];
    const float* bf    = (const float*)d_in[10];
    float* out = (float*)d_out;

    prologue_kernel<<<193, dim3(32, 32)>>>(query, Wq, bq, Wk, Wv, bv, Wf, bf);

    attn_main_kernel<<<592, 256>>>(
        reinterpret_cast<const ulonglong2*>(key),
        reinterpret_cast<const ulonglong2*>(value),
        out);
}